// round 12
// baseline (speedup 1.0000x reference)
#include <cuda_runtime.h>
#include <cuda_bf16.h>
#include <stdint.h>

// Edge MLP, factored: h1[e] = relu(P[src]+Q'[dst]); P=node@W1[:64], Q'=node@W1[64:]+b1.
// R12: TILE_M=64 -> 69.6KB smem/CTA -> 3 CTAs/SM (was 2; kernel latency-bound at occ 24%).
// Warp-specialized split-N (wid0-3: N[0,64)+finalize, wid4-7: N[64,128)+gather), LDSM frags.

#define TILE_M 64
#define SW 136
#define SWA 72
#define THREADS 256
#define MAX_NODES 100352

__device__ __nv_bfloat16 g_P[(size_t)MAX_NODES * 128];
__device__ __nv_bfloat16 g_Q[(size_t)MAX_NODES * 128];

__device__ __forceinline__ unsigned pack_bf16(float lo, float hi) {
    unsigned r;
    asm("cvt.rn.bf16x2.f32 %0, %1, %2;" : "=r"(r) : "f"(hi), "f"(lo));
    return r;
}
__device__ __forceinline__ unsigned add2relu(unsigned a, unsigned b) {
    unsigned r;
    asm("add.rn.bf16x2 %0, %1, %2;" : "=r"(r) : "r"(a), "r"(b));
    asm("max.bf16x2 %0, %0, %1;" : "+r"(r) : "r"(0u));
    return r;
}
__device__ __forceinline__ void mma16816(float c[4],
                                         unsigned a0, unsigned a1, unsigned a2, unsigned a3,
                                         unsigned b0, unsigned b1) {
    asm volatile(
        "mma.sync.aligned.m16n8k16.row.col.f32.bf16.bf16.f32 "
        "{%0,%1,%2,%3}, {%4,%5,%6,%7}, {%8,%9}, {%0,%1,%2,%3};\n"
        : "+f"(c[0]), "+f"(c[1]), "+f"(c[2]), "+f"(c[3])
        : "r"(a0), "r"(a1), "r"(a2), "r"(a3), "r"(b0), "r"(b1));
}
__device__ __forceinline__ void ldsm4(unsigned r[4], uint32_t addr) {
    asm volatile("ldmatrix.sync.aligned.m8n8.x4.shared.b16 {%0,%1,%2,%3}, [%4];"
                 : "=r"(r[0]), "=r"(r[1]), "=r"(r[2]), "=r"(r[3]) : "r"(addr));
}

// ---------------- precompute: P = node@W1[:64], Q = node@W1[64:] + b1 (unchanged R11) ----
#define PQ_W1    0
#define PQ_A     34816
#define PQ_STAGE (PQ_A + 128 * SWA * 2)
#define PQ_B1    (PQ_STAGE + 128 * SW * 2)
#define PQ_SMEM  (PQ_B1 + 512)

extern "C" __global__ void __launch_bounds__(128, 2)
pq_precompute(const float* __restrict__ node_rep, const float* __restrict__ W1,
              const float* __restrict__ b1, int N, int ntiles) {
    extern __shared__ char smem_raw[];
    __nv_bfloat16* w1t   = reinterpret_cast<__nv_bfloat16*>(smem_raw + PQ_W1);
    __nv_bfloat16* a     = reinterpret_cast<__nv_bfloat16*>(smem_raw + PQ_A);
    __nv_bfloat16* stage = reinterpret_cast<__nv_bfloat16*>(smem_raw + PQ_STAGE);
    float* b1s = reinterpret_cast<float*>(smem_raw + PQ_B1);

    const int tid  = threadIdx.x;
    const int lane = tid & 31;
    const int warp = tid >> 5;

    for (int i = tid; i < 128 * 128; i += 128) {
        int k = i >> 7, n = i & 127;
        w1t[n * SW + k] = __float2bfloat16(W1[i]);
    }
    if (tid < 128) b1s[tid] = b1[tid];
    __syncthreads();

    const int q  = lane & 3;
    const int g4 = lane >> 2;
    const int r0 = (warp << 5) + g4;

    for (int tile = blockIdx.x; tile < ntiles; tile += gridDim.x) {
        const int base = tile * 128;

        for (int idx = tid; idx < 128 * 16; idx += 128) {
            const int row = idx >> 4, seg = idx & 15;
            int node = base + row; if (node >= N) node = N - 1;
            const float4 v = reinterpret_cast<const float4*>(node_rep + (long long)node * 64)[seg];
            uint64_t dv = ((uint64_t)pack_bf16(v.z, v.w) << 32) | pack_bf16(v.x, v.y);
            *reinterpret_cast<uint64_t*>(a + row * SWA + seg * 4) = dv;
        }
        __syncthreads();

        #pragma unroll
        for (int h = 0; h < 2; h++) {
            float acc[2][16][4];
            #pragma unroll
            for (int b = 0; b < 2; b++)
                #pragma unroll
                for (int t = 0; t < 16; t++)
                    #pragma unroll
                    for (int j = 0; j < 4; j++) acc[b][t][j] = 0.f;

            #pragma unroll
            for (int kt = 0; kt < 4; kt++) {
                const int kc = kt * 16 + 2 * q;
                unsigned af[2][4];
                #pragma unroll
                for (int b = 0; b < 2; b++) {
                    const int rb = r0 + 16 * b;
                    af[b][0] = *reinterpret_cast<const unsigned*>(a + rb * SWA + kc);
                    af[b][1] = *reinterpret_cast<const unsigned*>(a + (rb + 8) * SWA + kc);
                    af[b][2] = *reinterpret_cast<const unsigned*>(a + rb * SWA + kc + 8);
                    af[b][3] = *reinterpret_cast<const unsigned*>(a + (rb + 8) * SWA + kc + 8);
                }
                #pragma unroll
                for (int t = 0; t < 16; t++) {
                    const int n = t * 8 + g4;
                    const unsigned b0 = *reinterpret_cast<const unsigned*>(w1t + n * SW + 64 * h + kc);
                    const unsigned b1r = *reinterpret_cast<const unsigned*>(w1t + n * SW + 64 * h + kc + 8);
                    mma16816(acc[0][t], af[0][0], af[0][1], af[0][2], af[0][3], b0, b1r);
                    mma16816(acc[1][t], af[1][0], af[1][1], af[1][2], af[1][3], b0, b1r);
                }
            }

            const float bsc = h ? 1.f : 0.f;
            #pragma unroll
            for (int b = 0; b < 2; b++) {
                const int rr = r0 + 16 * b;
                #pragma unroll
                for (int t = 0; t < 16; t++) {
                    const int c = t * 8 + 2 * q;
                    const float bl = bsc * b1s[c], bh = bsc * b1s[c + 1];
                    *reinterpret_cast<unsigned*>(stage + rr * SW + c) =
                        pack_bf16(acc[b][t][0] + bl, acc[b][t][1] + bh);
                    *reinterpret_cast<unsigned*>(stage + (rr + 8) * SW + c) =
                        pack_bf16(acc[b][t][2] + bl, acc[b][t][3] + bh);
                }
            }
            __syncthreads();

            __nv_bfloat16* outp = h ? g_Q : g_P;
            for (int idx = tid; idx < 128 * 16; idx += 128) {
                const int row = idx >> 4, seg = idx & 15;
                if (base + row < N) {
                    const uint4 v = *reinterpret_cast<const uint4*>(stage + row * SW + seg * 8);
                    *reinterpret_cast<uint4*>(outp + (long long)(base + row) * 128 + seg * 8) = v;
                }
            }
            __syncthreads();
        }
    }
}

// ---------------- main ----------------
#define SM_W2    0
#define SM_FEAT0 34816
#define SM_FEAT1 (34816 + 16384)
#define SM_F32   (34816 + 32768)
#define SM_DD    (SM_F32 + 1024)
#define SMEM_BYTES (SM_DD + 1024)          // 69632 B -> 3 CTAs/SM

__device__ __forceinline__ uint32_t feat_addr(uint32_t fbase, int row, int gran, int within) {
    return fbase + (uint32_t)row * 256u + (uint32_t)((gran ^ (row & 7)) << 4) + (uint32_t)within;
}
__device__ __forceinline__ uint32_t smem_u32(const void* p) {
    uint32_t a;
    asm("{ .reg .u64 t; cvta.to.shared.u64 t, %1; cvt.u32.u64 %0, t; }" : "=r"(a) : "l"(p));
    return a;
}

// producer: 2 threads per edge; thread half h covers output bytes [128h,128h+128)
__device__ __forceinline__ void produce_tile(uint32_t fbase, int base, int E,
                                             const int* __restrict__ eidx,
                                             int edge, int h) {
    const int e = base + edge;
    int src = 0, dst = 0;
    if (e < E) { src = eidx[e]; dst = eidx[E + e]; }
    const uint4* Pp = reinterpret_cast<const uint4*>(g_P + (long long)src * 128) + 8 * h;
    const uint4* Qp = reinterpret_cast<const uint4*>(g_Q + (long long)dst * 128) + 8 * h;
    uint4 pv[8], qv[8];
    #pragma unroll
    for (int i = 0; i < 8; i++) pv[i] = Pp[i];
    #pragma unroll
    for (int i = 0; i < 8; i++) qv[i] = Qp[i];
    #pragma unroll
    for (int i = 0; i < 8; i++) {
        uint4 o;
        o.x = add2relu(pv[i].x, qv[i].x); o.y = add2relu(pv[i].y, qv[i].y);
        o.z = add2relu(pv[i].z, qv[i].z); o.w = add2relu(pv[i].w, qv[i].w);
        const uint32_t ad = feat_addr(fbase, edge, 8 * h + i, 0);
        asm volatile("st.shared.v4.b32 [%0], {%1,%2,%3,%4};"
                     :: "r"(ad), "r"(o.x), "r"(o.y), "r"(o.z), "r"(o.w) : "memory");
    }
}

extern "C" __global__ void __launch_bounds__(THREADS, 3)
graphormer_edge_mlp(const int* __restrict__ eidx,
                    const float* __restrict__ W2, const float* __restrict__ b2,
                    const float* __restrict__ W3, const float* __restrict__ b3,
                    float* __restrict__ out,
                    int E, int num_tiles) {
    extern __shared__ char smem_raw[];
    __nv_bfloat16* w2t = reinterpret_cast<__nv_bfloat16*>(smem_raw + SM_W2);
    float* b2s = reinterpret_cast<float*>(smem_raw + SM_F32);
    float* w3s = b2s + 128;
    float* ddf = reinterpret_cast<float*>(smem_raw + SM_DD);   // [2 buf][2 half][64 rows]
    const uint32_t sb = smem_u32(smem_raw);
    const uint32_t fb[2] = { sb + SM_FEAT0, sb + SM_FEAT1 };
    const uint32_t wb = sb + SM_W2;

    const int tid  = threadIdx.x;
    const int lane = tid & 31;
    const int wid  = tid >> 5;

    for (int i = tid; i < 128 * 128; i += THREADS) {
        int k = i >> 7, n = i & 127;
        w2t[n * SW + k] = __float2bfloat16(W2[i]);
    }
    if (tid < 128) { b2s[tid] = b2[tid]; w3s[tid] = W3[tid]; }
    const float bb3 = b3[0];

    const bool is_prod = (wid >= 4);
    const int ptid = tid - 128;
    const int pedge = ptid >> 1, ph = ptid & 1;   // producer: edge, byte-half

    const int q  = lane & 3;
    const int g4 = lane >> 2;
    const int mwarp = wid & 3;
    const int r0blk = mwarp << 4;                 // 16-row block per warp (TILE 64)
    const int r0 = r0blk + g4;
    const int ch = is_prod ? 1 : 0;               // N-half

    // LDSM lane-addressing
    const int arow = lane & 15;
    const int ghi  = lane >> 4;
    const int ax   = arow & 7;
    const uint32_t arow0 = (uint32_t)(r0blk + arow) * 256u;
    uint32_t bbase[4];
    #pragma unroll
    for (int j = 0; j < 4; j++) {
        const int n = (ch * 8 + 2 * j + ghi) * 8 + (lane & 7);
        bbase[j] = wb + (uint32_t)n * (SW * 2) + (uint32_t)(((lane >> 3) & 1) * 16);
    }

    __syncthreads();
    if (is_prod)
        produce_tile(fb[0], blockIdx.x * TILE_M, E, eidx, pedge, ph);
    __syncthreads();

    int buf = 0;
    int prev_base = -1;
    for (int tile = blockIdx.x; tile < num_tiles; tile += gridDim.x) {
        const int base = tile * TILE_M;

        if (!is_prod && prev_base >= 0 && tid < 64) {
            const int e = prev_base + tid;
            if (e < E) {
                const float d = ddf[(buf ^ 1) * 128 + tid] + ddf[(buf ^ 1) * 128 + 64 + tid];
                out[e] = 1.f / (1.f + __expf(-(d + bb3)));
            }
        }

        // ---- GEMM: own N-half, rows r0blk..r0blk+15 ----
        {
            const uint32_t f = fb[buf];
            float acc[8][4];
            #pragma unroll
            for (int t = 0; t < 8; t++)
                #pragma unroll
                for (int j = 0; j < 4; j++) acc[t][j] = 0.f;

            #pragma unroll
            for (int kt = 0; kt < 8; kt++) {
                const uint32_t goff = (uint32_t)(((2 * kt + ghi) ^ ax) << 4);
                unsigned a[4];
                ldsm4(a, f + arow0 + goff);
                #pragma unroll
                for (int j = 0; j < 4; j++) {
                    unsigned bbr[4];
                    ldsm4(bbr, bbase[j] + kt * 32);
                    mma16816(acc[2 * j],     a[0], a[1], a[2], a[3], bbr[0], bbr[1]);
                    mma16816(acc[2 * j + 1], a[0], a[1], a[2], a[3], bbr[2], bbr[3]);
                }
            }

            float d0 = 0.f, d1 = 0.f;
            #pragma unroll
            for (int t = 0; t < 8; t++) {
                const int c = (ch * 8 + t) * 8 + 2 * q;
                const float wa = w3s[c], wbv = w3s[c + 1];
                d0 += fmaxf(acc[t][0] + b2s[c], 0.f) * wa
                    + fmaxf(acc[t][1] + b2s[c + 1], 0.f) * wbv;
                d1 += fmaxf(acc[t][2] + b2s[c], 0.f) * wa
                    + fmaxf(acc[t][3] + b2s[c + 1], 0.f) * wbv;
            }
            d0 += __shfl_xor_sync(0xFFFFFFFFu, d0, 1);
            d0 += __shfl_xor_sync(0xFFFFFFFFu, d0, 2);
            d1 += __shfl_xor_sync(0xFFFFFFFFu, d1, 1);
            d1 += __shfl_xor_sync(0xFFFFFFFFu, d1, 2);
            if (q == 0) {
                ddf[buf * 128 + ch * 64 + r0]     = d0;
                ddf[buf * 128 + ch * 64 + r0 + 8] = d1;
            }
        }

        if (is_prod) {
            const int ntile = tile + gridDim.x;
            if (ntile < num_tiles)
                produce_tile(fb[buf ^ 1], ntile * TILE_M, E, eidx, pedge, ph);
        }

        __syncthreads();
        prev_base = base;
        buf ^= 1;
    }

    if (!is_prod && prev_base >= 0 && tid < 64) {
        const int e = prev_base + tid;
        if (e < E) {
            const float d = ddf[(buf ^ 1) * 128 + tid] + ddf[(buf ^ 1) * 128 + 64 + tid];
            out[e] = 1.f / (1.f + __expf(-(d + bb3)));
        }
    }
}

extern "C" void kernel_launch(void* const* d_in, const int* in_sizes, int n_in,
                              void* d_out, int out_size) {
    const float* node_rep = (const float*)d_in[0];
    const int*   eidx     = (const int*)d_in[1];
    const float* W1       = (const float*)d_in[2];
    const float* b1       = (const float*)d_in[3];
    const float* W2       = (const float*)d_in[4];
    const float* b2       = (const float*)d_in[5];
    const float* W3       = (const float*)d_in[6];
    const float* b3       = (const float*)d_in[7];
    float*       out      = (float*)d_out;

    const int N = in_sizes[0] / 64;
    const int E = in_sizes[1] / 2;
    const int ntiles_pq = (N + 127) / 128;
    const int num_tiles = (E + TILE_M - 1) / TILE_M;

    cudaFuncSetAttribute(pq_precompute,
                         cudaFuncAttributeMaxDynamicSharedMemorySize, PQ_SMEM);
    cudaFuncSetAttribute(graphormer_edge_mlp,
                         cudaFuncAttributeMaxDynamicSharedMemorySize, SMEM_BYTES);

    int g1 = ntiles_pq < 296 ? ntiles_pq : 296;
    pq_precompute<<<g1, 128, PQ_SMEM>>>(node_rep, W1, b1, N, ntiles_pq);

    int g2 = num_tiles < 444 ? num_tiles : 444;
    graphormer_edge_mlp<<<g2, THREADS, SMEM_BYTES>>>(
        eidx, W2, b2, W3, b3, out, E, num_tiles);
}

// round 13
// speedup vs baseline: 1.0898x; 1.0898x over previous
#include <cuda_runtime.h>
#include <cuda_bf16.h>
#include <stdint.h>

// Edge MLP, factored: h1[e] = relu(P[src]+Q'[dst]); P=node@W1[:64], Q'=node@W1[64:]+b1.
// R13: W2 B-fragments held in REGISTERS (tile-invariant; 32 regs/thread) -> no w2t SMEM
// -> 72KB/CTA -> 3 CTAs/SM. Each warp: 16 cols x 128 rows, m-blocks serial, dot-reduced.

#define TILE_M 128
#define SW 136
#define SWA 72
#define THREADS 256
#define MAX_NODES 100352

__device__ __nv_bfloat16 g_P[(size_t)MAX_NODES * 128];
__device__ __nv_bfloat16 g_Q[(size_t)MAX_NODES * 128];

__device__ __forceinline__ unsigned pack_bf16(float lo, float hi) {
    unsigned r;
    asm("cvt.rn.bf16x2.f32 %0, %1, %2;" : "=r"(r) : "f"(hi), "f"(lo));
    return r;
}
__device__ __forceinline__ unsigned add2relu(unsigned a, unsigned b) {
    unsigned r;
    asm("add.rn.bf16x2 %0, %1, %2;" : "=r"(r) : "r"(a), "r"(b));
    asm("max.bf16x2 %0, %0, %1;" : "+r"(r) : "r"(0u));
    return r;
}
__device__ __forceinline__ void mma16816(float c[4],
                                         unsigned a0, unsigned a1, unsigned a2, unsigned a3,
                                         unsigned b0, unsigned b1) {
    asm volatile(
        "mma.sync.aligned.m16n8k16.row.col.f32.bf16.bf16.f32 "
        "{%0,%1,%2,%3}, {%4,%5,%6,%7}, {%8,%9}, {%0,%1,%2,%3};\n"
        : "+f"(c[0]), "+f"(c[1]), "+f"(c[2]), "+f"(c[3])
        : "r"(a0), "r"(a1), "r"(a2), "r"(a3), "r"(b0), "r"(b1));
}
__device__ __forceinline__ void ldsm4(unsigned r[4], uint32_t addr) {
    asm volatile("ldmatrix.sync.aligned.m8n8.x4.shared.b16 {%0,%1,%2,%3}, [%4];"
                 : "=r"(r[0]), "=r"(r[1]), "=r"(r[2]), "=r"(r[3]) : "r"(addr));
}

// ---------------- precompute: P = node@W1[:64], Q = node@W1[64:] + b1 (R11, proven) ----
#define PQ_W1    0
#define PQ_A     34816
#define PQ_STAGE (PQ_A + 128 * SWA * 2)
#define PQ_B1    (PQ_STAGE + 128 * SW * 2)
#define PQ_SMEM  (PQ_B1 + 512)

extern "C" __global__ void __launch_bounds__(128, 2)
pq_precompute(const float* __restrict__ node_rep, const float* __restrict__ W1,
              const float* __restrict__ b1, int N, int ntiles) {
    extern __shared__ char smem_raw[];
    __nv_bfloat16* w1t   = reinterpret_cast<__nv_bfloat16*>(smem_raw + PQ_W1);
    __nv_bfloat16* a     = reinterpret_cast<__nv_bfloat16*>(smem_raw + PQ_A);
    __nv_bfloat16* stage = reinterpret_cast<__nv_bfloat16*>(smem_raw + PQ_STAGE);
    float* b1s = reinterpret_cast<float*>(smem_raw + PQ_B1);

    const int tid  = threadIdx.x;
    const int lane = tid & 31;
    const int warp = tid >> 5;

    for (int i = tid; i < 128 * 128; i += 128) {
        int k = i >> 7, n = i & 127;
        w1t[n * SW + k] = __float2bfloat16(W1[i]);
    }
    if (tid < 128) b1s[tid] = b1[tid];
    __syncthreads();

    const int q  = lane & 3;
    const int g4 = lane >> 2;
    const int r0 = (warp << 5) + g4;

    for (int tile = blockIdx.x; tile < ntiles; tile += gridDim.x) {
        const int base = tile * 128;

        for (int idx = tid; idx < 128 * 16; idx += 128) {
            const int row = idx >> 4, seg = idx & 15;
            int node = base + row; if (node >= N) node = N - 1;
            const float4 v = reinterpret_cast<const float4*>(node_rep + (long long)node * 64)[seg];
            uint64_t dv = ((uint64_t)pack_bf16(v.z, v.w) << 32) | pack_bf16(v.x, v.y);
            *reinterpret_cast<uint64_t*>(a + row * SWA + seg * 4) = dv;
        }
        __syncthreads();

        #pragma unroll
        for (int h = 0; h < 2; h++) {
            float acc[2][16][4];
            #pragma unroll
            for (int b = 0; b < 2; b++)
                #pragma unroll
                for (int t = 0; t < 16; t++)
                    #pragma unroll
                    for (int j = 0; j < 4; j++) acc[b][t][j] = 0.f;

            #pragma unroll
            for (int kt = 0; kt < 4; kt++) {
                const int kc = kt * 16 + 2 * q;
                unsigned af[2][4];
                #pragma unroll
                for (int b = 0; b < 2; b++) {
                    const int rb = r0 + 16 * b;
                    af[b][0] = *reinterpret_cast<const unsigned*>(a + rb * SWA + kc);
                    af[b][1] = *reinterpret_cast<const unsigned*>(a + (rb + 8) * SWA + kc);
                    af[b][2] = *reinterpret_cast<const unsigned*>(a + rb * SWA + kc + 8);
                    af[b][3] = *reinterpret_cast<const unsigned*>(a + (rb + 8) * SWA + kc + 8);
                }
                #pragma unroll
                for (int t = 0; t < 16; t++) {
                    const int n = t * 8 + g4;
                    const unsigned b0 = *reinterpret_cast<const unsigned*>(w1t + n * SW + 64 * h + kc);
                    const unsigned b1r = *reinterpret_cast<const unsigned*>(w1t + n * SW + 64 * h + kc + 8);
                    mma16816(acc[0][t], af[0][0], af[0][1], af[0][2], af[0][3], b0, b1r);
                    mma16816(acc[1][t], af[1][0], af[1][1], af[1][2], af[1][3], b0, b1r);
                }
            }

            const float bsc = h ? 1.f : 0.f;
            #pragma unroll
            for (int b = 0; b < 2; b++) {
                const int rr = r0 + 16 * b;
                #pragma unroll
                for (int t = 0; t < 16; t++) {
                    const int c = t * 8 + 2 * q;
                    const float bl = bsc * b1s[c], bh = bsc * b1s[c + 1];
                    *reinterpret_cast<unsigned*>(stage + rr * SW + c) =
                        pack_bf16(acc[b][t][0] + bl, acc[b][t][1] + bh);
                    *reinterpret_cast<unsigned*>(stage + (rr + 8) * SW + c) =
                        pack_bf16(acc[b][t][2] + bl, acc[b][t][3] + bh);
                }
            }
            __syncthreads();

            __nv_bfloat16* outp = h ? g_Q : g_P;
            for (int idx = tid; idx < 128 * 16; idx += 128) {
                const int row = idx >> 4, seg = idx & 15;
                if (base + row < N) {
                    const uint4 v = *reinterpret_cast<const uint4*>(stage + row * SW + seg * 8);
                    *reinterpret_cast<uint4*>(outp + (long long)(base + row) * 128 + seg * 8) = v;
                }
            }
            __syncthreads();
        }
    }
}

// ---------------- main ----------------
#define SM_FEAT0 0
#define SM_FEAT1 32768
#define SM_DD    65536
#define SMEM_BYTES (65536 + 8192)     // 72KB -> 3 CTAs/SM

__device__ __forceinline__ uint32_t feat_addr(uint32_t fbase, int row, int gran) {
    return fbase + (uint32_t)row * 256u + (uint32_t)((gran ^ (row & 7)) << 4);
}
__device__ __forceinline__ uint32_t smem_u32(const void* p) {
    uint32_t a;
    asm("{ .reg .u64 t; cvta.to.shared.u64 t, %1; cvt.u32.u64 %0, t; }" : "=r"(a) : "l"(p));
    return a;
}

// all threads gather: 1 thread = 1 edge-half (128 B of the h1 row)
__device__ __forceinline__ void produce_tile(uint32_t fbase, int base, int E,
                                             const int* __restrict__ eidx,
                                             int edge, int h) {
    const int e = base + edge;
    int src = 0, dst = 0;
    if (e < E) { src = eidx[e]; dst = eidx[E + e]; }
    const uint4* Pp = reinterpret_cast<const uint4*>(g_P + (long long)src * 128) + 8 * h;
    const uint4* Qp = reinterpret_cast<const uint4*>(g_Q + (long long)dst * 128) + 8 * h;
    #pragma unroll
    for (int i = 0; i < 8; i += 2) {
        const uint4 p0 = Pp[i], p1 = Pp[i + 1];
        const uint4 q0 = Qp[i], q1 = Qp[i + 1];
        uint4 o0, o1;
        o0.x = add2relu(p0.x, q0.x); o0.y = add2relu(p0.y, q0.y);
        o0.z = add2relu(p0.z, q0.z); o0.w = add2relu(p0.w, q0.w);
        o1.x = add2relu(p1.x, q1.x); o1.y = add2relu(p1.y, q1.y);
        o1.z = add2relu(p1.z, q1.z); o1.w = add2relu(p1.w, q1.w);
        const uint32_t a0 = feat_addr(fbase, edge, 8 * h + i);
        const uint32_t a1 = feat_addr(fbase, edge, 8 * h + i + 1);
        asm volatile("st.shared.v4.b32 [%0], {%1,%2,%3,%4};"
                     :: "r"(a0), "r"(o0.x), "r"(o0.y), "r"(o0.z), "r"(o0.w) : "memory");
        asm volatile("st.shared.v4.b32 [%0], {%1,%2,%3,%4};"
                     :: "r"(a1), "r"(o1.x), "r"(o1.y), "r"(o1.z), "r"(o1.w) : "memory");
    }
}

extern "C" __global__ void __launch_bounds__(THREADS, 3)
graphormer_edge_mlp(const int* __restrict__ eidx,
                    const float* __restrict__ W2, const float* __restrict__ b2,
                    const float* __restrict__ W3, const float* __restrict__ b3,
                    float* __restrict__ out,
                    int E, int num_tiles) {
    extern __shared__ char smem_raw[];
    float* ddf = reinterpret_cast<float*>(smem_raw + SM_DD);  // [2 buf][8 cg][128 rows]
    const uint32_t sb = smem_u32(smem_raw);
    const uint32_t fb[2] = { sb + SM_FEAT0, sb + SM_FEAT1 };

    const int tid  = threadIdx.x;
    const int lane = tid & 31;
    const int wid  = tid >> 5;

    const int q  = lane & 3;
    const int g4 = lane >> 2;

    // ---- B fragments (W2, tile-invariant) and epilogue scalars -> registers ----
    unsigned breg[8][2][2];
    float waj[2][2], bbj[2][2];
    #pragma unroll
    for (int kt = 0; kt < 8; kt++) {
        const int k0 = kt * 16 + 2 * q;
        #pragma unroll
        for (int j = 0; j < 2; j++) {
            const int n = 16 * wid + 8 * j + g4;
            breg[kt][j][0] = pack_bf16(W2[k0 * 128 + n],       W2[(k0 + 1) * 128 + n]);
            breg[kt][j][1] = pack_bf16(W2[(k0 + 8) * 128 + n], W2[(k0 + 9) * 128 + n]);
        }
    }
    #pragma unroll
    for (int j = 0; j < 2; j++) {
        const int c = 16 * wid + 8 * j + 2 * q;
        waj[j][0] = W3[c];  waj[j][1] = W3[c + 1];
        bbj[j][0] = b2[c];  bbj[j][1] = b2[c + 1];
    }
    const float bb3 = b3[0];

    // ldsm A addressing
    const int arow = lane & 15;
    const int ghi  = lane >> 4;
    const int ax   = arow & 7;

    // gather role
    const int gedge = tid >> 1, gh = tid & 1;

    produce_tile(fb[0], blockIdx.x * TILE_M, E, eidx, gedge, gh);
    __syncthreads();

    int buf = 0;
    int prev_base = -1;
    for (int tile = blockIdx.x; tile < num_tiles; tile += gridDim.x) {
        const int base = tile * TILE_M;

        // ---- finalize previous tile ----
        if (prev_base >= 0 && tid < 128) {
            const int e = prev_base + tid;
            if (e < E) {
                const float* dp = ddf + (buf ^ 1) * 1024 + tid;
                float s = dp[0];
                #pragma unroll
                for (int cg = 1; cg < 8; cg++) s += dp[cg * 128];
                out[e] = 1.f / (1.f + __expf(-(s + bb3)));
            }
        }

        // ---- MMA: this warp's 16 cols x all 128 rows, m-blocks serial ----
        {
            const uint32_t f = fb[buf];
            #pragma unroll
            for (int mb = 0; mb < 8; mb++) {
                float acc[2][4];
                #pragma unroll
                for (int j = 0; j < 2; j++)
                    #pragma unroll
                    for (int x = 0; x < 4; x++) acc[j][x] = 0.f;

                const uint32_t rbase = (uint32_t)(16 * mb + arow) * 256u + fb[buf];
                #pragma unroll
                for (int kt = 0; kt < 8; kt++) {
                    unsigned a[4];
                    ldsm4(a, rbase + (uint32_t)(((2 * kt + ghi) ^ ax) << 4));
                    mma16816(acc[0], a[0], a[1], a[2], a[3], breg[kt][0][0], breg[kt][0][1]);
                    mma16816(acc[1], a[0], a[1], a[2], a[3], breg[kt][1][0], breg[kt][1][1]);
                }

                float d0 = fmaxf(acc[0][0] + bbj[0][0], 0.f) * waj[0][0]
                         + fmaxf(acc[0][1] + bbj[0][1], 0.f) * waj[0][1]
                         + fmaxf(acc[1][0] + bbj[1][0], 0.f) * waj[1][0]
                         + fmaxf(acc[1][1] + bbj[1][1], 0.f) * waj[1][1];
                float d1 = fmaxf(acc[0][2] + bbj[0][0], 0.f) * waj[0][0]
                         + fmaxf(acc[0][3] + bbj[0][1], 0.f) * waj[0][1]
                         + fmaxf(acc[1][2] + bbj[1][0], 0.f) * waj[1][0]
                         + fmaxf(acc[1][3] + bbj[1][1], 0.f) * waj[1][1];
                d0 += __shfl_xor_sync(0xFFFFFFFFu, d0, 1);
                d0 += __shfl_xor_sync(0xFFFFFFFFu, d0, 2);
                d1 += __shfl_xor_sync(0xFFFFFFFFu, d1, 1);
                d1 += __shfl_xor_sync(0xFFFFFFFFu, d1, 2);
                if (q == 0) {
                    ddf[buf * 1024 + wid * 128 + 16 * mb + g4]     = d0;
                    ddf[buf * 1024 + wid * 128 + 16 * mb + g4 + 8] = d1;
                }
            }
            (void)f;
        }

        // ---- gather next tile into other buffer ----
        {
            const int ntile = tile + gridDim.x;
            if (ntile < num_tiles)
                produce_tile(fb[buf ^ 1], ntile * TILE_M, E, eidx, gedge, gh);
        }

        __syncthreads();
        prev_base = base;
        buf ^= 1;
    }

    // ---- finalize last tile ----
    if (prev_base >= 0 && tid < 128) {
        const int e = prev_base + tid;
        if (e < E) {
            const float* dp = ddf + (buf ^ 1) * 1024 + tid;
            float s = dp[0];
            #pragma unroll
            for (int cg = 1; cg < 8; cg++) s += dp[cg * 128];
            out[e] = 1.f / (1.f + __expf(-(s + bb3)));
        }
    }
}

extern "C" void kernel_launch(void* const* d_in, const int* in_sizes, int n_in,
                              void* d_out, int out_size) {
    const float* node_rep = (const float*)d_in[0];
    const int*   eidx     = (const int*)d_in[1];
    const float* W1       = (const float*)d_in[2];
    const float* b1       = (const float*)d_in[3];
    const float* W2       = (const float*)d_in[4];
    const float* b2       = (const float*)d_in[5];
    const float* W3       = (const float*)d_in[6];
    const float* b3       = (const float*)d_in[7];
    float*       out      = (float*)d_out;

    const int N = in_sizes[0] / 64;
    const int E = in_sizes[1] / 2;
    const int ntiles_pq = (N + 127) / 128;
    const int num_tiles = (E + TILE_M - 1) / TILE_M;

    cudaFuncSetAttribute(pq_precompute,
                         cudaFuncAttributeMaxDynamicSharedMemorySize, PQ_SMEM);
    cudaFuncSetAttribute(graphormer_edge_mlp,
                         cudaFuncAttributeMaxDynamicSharedMemorySize, SMEM_BYTES);

    int g1 = ntiles_pq < 296 ? ntiles_pq : 296;
    pq_precompute<<<g1, 128, PQ_SMEM>>>(node_rep, W1, b1, N, ntiles_pq);

    int g2 = num_tiles < 444 ? num_tiles : 444;
    graphormer_edge_mlp<<<g2, THREADS, SMEM_BYTES>>>(
        eidx, W2, b2, W3, b3, out, E, num_tiles);
}